// round 8
// baseline (speedup 1.0000x reference)
#include <cuda_runtime.h>
#include <cuda_fp16.h>
#include <cstdint>

// ---------------- constants ----------------
#define NVAR   64
#define HID1   256
#define HID2   128
#define BATCH  16384
#define BT     128
#define NCTA   (BATCH / BT)        // 128 CTAs
#define NCHUNK 256
#define KTMAX  5
#define W2H    8192                // halfs per W2 chunk
#define AS     88                  // Ac row stride (halfs)
#define HS     72                  // sH row stride (halfs)
#define W1SLOT 10240               // bytes per W1 smem buffer (KTMAX*1024*2)

// SMEM byte offsets
#define OFF_AC 0                          // 128 x 88 halfs = 22528
#define OFF_YC 22528                      // 64 x 128 halfs = 16384
#define OFF_H  38912                      // 2 x (128x72x2) = 36864
#define OFF_W1 75776                      // 2 x 10240      = 20480
#define OFF_W2 96256                      // 2 x 16384      = 32768
#define OFF_B1 129024                     // 2 x 256 f
#define OFF_B2 131072                     // 2 x 128 f
#define OFF_W3 132096                     // 2 x 128 f
#define OFF_B3 133120                     // 2 f (+pad)
#define OFF_SP 133136                     // 2 x 128 f
#define SMEM_TOTAL 134160
#define HBUF   18432

// ---------------- device scratch ----------------
__device__ __half g_W1h[NVAR * 4 * KTMAX * 1024];  // packed variable-length chunks
__device__ __half g_W2h[NCHUNK * W2H];
__device__ __half g_Uth[NVAR * BATCH];
__device__ int    g_plist[NVAR * NVAR];
__device__ int    g_pcnt[NVAR];
__device__ int    g_KT[NVAR];
__device__ int    g_off1[NVAR];

// ---------------- helpers ----------------
static __device__ __forceinline__ void mma16(float* c, const unsigned* a,
                                             unsigned b0, unsigned b1) {
    asm volatile(
        "mma.sync.aligned.m16n8k16.row.col.f32.f16.f16.f32 "
        "{%0,%1,%2,%3},{%4,%5,%6,%7},{%8,%9},{%0,%1,%2,%3};\n"
        : "+f"(c[0]), "+f"(c[1]), "+f"(c[2]), "+f"(c[3])
        : "r"(a[0]), "r"(a[1]), "r"(a[2]), "r"(a[3]), "r"(b0), "r"(b1));
}

static __device__ __forceinline__ void ldmA(unsigned* a, uint32_t saddr) {
    asm volatile("ldmatrix.sync.aligned.m8n8.x4.shared.b16 {%0,%1,%2,%3}, [%4];"
        : "=r"(a[0]), "=r"(a[1]), "=r"(a[2]), "=r"(a[3]) : "r"(saddr));
}

static __device__ __forceinline__ void cp16(void* sdst, const void* gsrc) {
    unsigned sa = (unsigned)__cvta_generic_to_shared(sdst);
    asm volatile("cp.async.cg.shared.global [%0], [%1], 16;\n" :: "r"(sa), "l"(gsrc));
}

#define CP_COMMIT() asm volatile("cp.async.commit_group;\n" ::: "memory")
#define CP_WAIT1()  asm volatile("cp.async.wait_group 1;\n" ::: "memory")

// ---------------- prep kernels ----------------
__global__ void sen_prep_meta(const int* __restrict__ G) {
    int i = threadIdx.x;
    int np = 0;
    for (int j = 0; j < i; ++j)
        if (G[j * NVAR + i] > 0) g_plist[i * NVAR + np++] = j;
    g_pcnt[i] = np;
    g_KT[i] = (np + 16) / 16;
    __syncthreads();
    if (i == 0) {
        int off = 0;
        for (int v = 0; v < NVAR; ++v) { g_off1[v] = off; off += 4 * g_KT[v] * 1024; }
    }
}

// W1 packed frag-major fp16, compact K (parents, then u, zero-pad to ktc*16).
// chunk(i,q): [n4=4][kt=ktc][lane=32][8 halfs]; n4 covers 16 cols (pair of n8).
__global__ void sen_prep_w1h(const float* __restrict__ W1) {
    int idx = blockIdx.x * blockDim.x + threadIdx.x;
    if (idx >= NVAR * 4 * KTMAX * 1024) return;
    int i    = idx / (4 * KTMAX * 1024);
    int rem  = idx % (4 * KTMAX * 1024);
    int q    = rem / (KTMAX * 1024);
    int rem2 = rem % (KTMAX * 1024);
    int n4   = rem2 / (KTMAX * 256);
    int rem3 = rem2 % (KTMAX * 256);
    int kt   = rem3 / 256;
    int f    = rem3 % 256;
    int lane = f >> 3, h = f & 7;
    int ktc = g_KT[i];
    if (kt >= ktc) return;
    int n8l = h >> 2, p = (h >> 1) & 1, e = h & 1;
    int k = kt * 16 + (lane & 3) * 2 + 8 * p + e;
    int n = q * 64 + n4 * 16 + n8l * 8 + (lane >> 2);
    int np = g_pcnt[i];
    float val = 0.f;
    if (k < np)       val = W1[(i * (NVAR + 1) + g_plist[i * NVAR + k]) * HID1 + n];
    else if (k == np) val = W1[(i * (NVAR + 1) + NVAR) * HID1 + n];
    int dst = g_off1[i] + q * ktc * 1024 + ((n4 * ktc + kt) * 32 + lane) * 8 + h;
    g_W1h[dst] = __float2half_rn(val);
}

// W2 frag-major fp16 (R6 layout): [n4=8][kt=4][lane=32][8 halfs]
__global__ void sen_prep_w2h(const float* __restrict__ W2) {
    int idx = blockIdx.x * blockDim.x + threadIdx.x;
    if (idx >= NCHUNK * W2H) return;
    int t    = idx / W2H;
    int rem  = idx % W2H;
    int n4   = rem / 1024;
    int rem2 = rem % 1024;
    int kt   = rem2 / 256;
    int f    = rem2 % 256;
    int lane = f >> 3, h = f & 7;
    int n8 = 2 * n4 + (h >> 2);
    int p  = (h >> 1) & 1, e = h & 1;
    int i = t >> 2, q = t & 3;
    int k = q * 64 + kt * 16 + (lane & 3) * 2 + 8 * p + e;
    int n = n8 * 8 + (lane >> 2);
    g_W2h[t * W2H + ((n4 * 4 + kt) * 32 + lane) * 8 + h] =
        __float2half_rn(W2[(i * HID1 + k) * HID2 + n]);
}

__global__ void sen_prep_ut(const float* __restrict__ U) {
    int idx = blockIdx.x * blockDim.x + threadIdx.x;
    if (idx >= NVAR * BATCH) return;
    int v = idx / BATCH;
    int b = idx - v * BATCH;
    g_Uth[idx] = __float2half_rn(U[b * NVAR + v]);
}

// ---------------- main kernel: 256 threads, BT=128 ----------------
__global__ void __launch_bounds__(256, 1) sen_main(
    const float* __restrict__ X,
    const float* __restrict__ b1g,
    const float* __restrict__ b2g,
    const float* __restrict__ W3g,
    const float* __restrict__ b3g,
    float* __restrict__ out)
{
    extern __shared__ char smem[];
    __half* Ac  = (__half*)(smem + OFF_AC);
    __half* Yc  = (__half*)(smem + OFF_YC);
    __half* sH  = (__half*)(smem + OFF_H);
    float*  sB1 = (float*)(smem + OFF_B1);
    float*  sB2 = (float*)(smem + OFF_B2);
    float*  sW3 = (float*)(smem + OFF_W3);
    float*  sB3 = (float*)(smem + OFF_B3);
    float*  sP  = (float*)(smem + OFF_SP);
    const uint32_t smb = (uint32_t)__cvta_generic_to_shared(smem);

    const int tid  = threadIdx.x;
    const int lane = tid & 31;
    const int w    = tid >> 5;
    const int wm   = w >> 1;                // M group 0..3 (rows 32*wm..+32)
    const int wn   = w & 1;                 // N group 0..1
    const int b0   = blockIdx.x * BT;
    const int r0   = 32 * wm + (lane >> 2);
    const int ccol = (lane & 3) * 2;

    const uint32_t aAb = smb + OFF_AC +
        ((((32 * wm + (lane & 15)) * AS) + (lane >> 4) * 8) << 1);
    const uint32_t aHb = smb + OFF_H +
        ((((32 * wm + (lane & 15)) * HS) + (lane >> 4) * 8) << 1);

    // init Yc (column-major fp16) from X
    for (int idx = tid; idx < NVAR * BT; idx += 256) {
        int v = idx >> 7, r = idx & 127;
        Yc[v * BT + r] = __float2half_rn(X[(size_t)(b0 + r) * NVAR + v]);
    }
    // var-0 biases (parity 0)
    sB1[tid] = __ldg(b1g + tid);
    if (tid < 128) { sB2[tid] = __ldg(b2g + tid); sW3[tid] = __ldg(W3g + tid); }
    if (tid == 0) sB3[0] = __ldg(b3g);
    __syncthreads();

    // gather Ac for var 0 (np=0 -> u at col 0, zeros elsewhere)
    {
        const int ktc0 = __ldg(g_KT);
        for (int idx = tid; idx < (ktc0 * 16) * BT; idx += 256) {
            int c = idx >> 7, r = idx & 127;
            Ac[r * AS + c] = (c == 0) ? g_Uth[b0 + r] : __half(0.f);
        }
        // prologue prefetch: W1(0,0) -> buf 0
        const char* s1 = (const char*)g_W1h;
        char* d1 = smem + OFF_W1;
        for (int idx = tid; idx < ktc0 * 128; idx += 256)
            cp16(d1 + idx * 16, s1 + idx * 16);
        CP_COMMIT();
    }

    float acc2[2][8][4];
    #pragma unroll
    for (int m = 0; m < 2; ++m)
        #pragma unroll
        for (int n = 0; n < 8; ++n)
            #pragma unroll
            for (int e = 0; e < 4; ++e) acc2[m][n][e] = 0.f;

    #pragma unroll 1
    for (int i = 0; i < NVAR; ++i) {
        const int pb  = i & 1;
        const int ktc = __ldg(g_KT + i);

        #pragma unroll 1
        for (int q = 0; q < 5; ++q) {
            // ---- prefetch (distance 1) ----
            {   // next L1 chunk: (i,q+1) / (i+1,0) / (i+1,1)
                int ni = (q < 3) ? i : i + 1;
                int nq = (q < 3) ? q + 1 : (q == 3 ? 0 : 1);
                if (ni < NVAR) {
                    int ktn = __ldg(g_KT + ni);
                    const char* s1 = (const char*)(g_W1h + __ldg(g_off1 + ni)
                                                   + nq * ktn * 1024);
                    char* d1 = smem + OFF_W1 + (nq & 1) * W1SLOT;
                    for (int idx = tid; idx < ktn * 128; idx += 256)
                        cp16(d1 + idx * 16, s1 + idx * 16);
                }
            }
            {   // next L2 chunk: consumed at step q+1
                int c2n = i * 4 + q;
                if (c2n < NCHUNK) {
                    const char* s2 = (const char*)(g_W2h + (size_t)c2n * W2H);
                    char* d2 = smem + OFF_W2 + (c2n & 1) * 16384;
                    for (int idx = tid; idx < 1024; idx += 256)
                        cp16(d2 + idx * 16, s2 + idx * 16);
                }
            }
            if (q == 0 && i + 1 < NVAR)
                sB1[((i + 1) & 1) * 256 + tid] = __ldg(b1g + (i + 1) * HID1 + tid);
            if (q == 1 && i + 1 < NVAR) {
                const int nb = (i + 1) & 1;
                if (tid < 128) {
                    sB2[nb * 128 + tid] = __ldg(b2g + (i + 1) * HID2 + tid);
                    sW3[nb * 128 + tid] = __ldg(W3g + (i + 1) * HID2 + tid);
                }
                if (tid == 0) sB3[nb] = __ldg(b3g + i + 1);
            }
            CP_COMMIT();
            CP_WAIT1();            // this step's W1/W2 landed
            __syncthreads();       // single barrier per step

            // ---- L1(q): c1 = Ac @ W1(i,q), warp tile 32M x 32N ----
            float c1[2][4][4];
            if (q < 4) {
                #pragma unroll
                for (int m = 0; m < 2; ++m)
                    #pragma unroll
                    for (int n = 0; n < 4; ++n)
                        #pragma unroll
                        for (int e = 0; e < 4; ++e) c1[m][n][e] = 0.f;
                const char* wb1 = smem + OFF_W1 + (q & 1) * W1SLOT;
                #pragma unroll 1
                for (int kt = 0; kt < ktc; ++kt) {
                    unsigned a0[4], a1[4];
                    ldmA(a0, aAb + kt * 32);
                    ldmA(a1, aAb + kt * 32 + 16 * AS * 2);
                    #pragma unroll
                    for (int n4 = 0; n4 < 2; ++n4) {
                        uint4 bb = *(const uint4*)(wb1 +
                            ((((wn * 2 + n4) * ktc + kt) * 32 + lane) << 4));
                        mma16(c1[0][2 * n4],     a0, bb.x, bb.y);
                        mma16(c1[0][2 * n4 + 1], a0, bb.z, bb.w);
                        mma16(c1[1][2 * n4],     a1, bb.x, bb.y);
                        mma16(c1[1][2 * n4 + 1], a1, bb.z, bb.w);
                    }
                }
            }

            // ---- L2(q-1): acc2 += sH[(q-1)&1] @ W2(i*4+q-1) ----
            if (q > 0) {
                const int c2 = i * 4 + q - 1;
                const char* wb2 = smem + OFF_W2 + (c2 & 1) * 16384;
                const uint32_t aH = aHb + ((q - 1) & 1) * HBUF;
                #pragma unroll
                for (int kt = 0; kt < 4; ++kt) {
                    unsigned a0[4], a1[4];
                    ldmA(a0, aH + kt * 32);
                    ldmA(a1, aH + kt * 32 + 16 * HS * 2);
                    #pragma unroll
                    for (int n4 = 0; n4 < 4; ++n4) {
                        uint4 bb = *(const uint4*)(wb2 +
                            ((((wn * 4 + n4) * 4 + kt) * 32 + lane) << 4));
                        mma16(acc2[0][2 * n4],     a0, bb.x, bb.y);
                        mma16(acc2[0][2 * n4 + 1], a0, bb.z, bb.w);
                        mma16(acc2[1][2 * n4],     a1, bb.x, bb.y);
                        mma16(acc2[1][2 * n4 + 1], a1, bb.z, bb.w);
                    }
                }
            }

            // ---- epilogue(q): +b1, relu, fp16 -> sH[q&1] ----
            if (q < 4) {
                __half* sHb = (__half*)(smem + OFF_H + (q & 1) * HBUF);
                const float* B1 = sB1 + pb * 256 + q * 64;
                #pragma unroll
                for (int Mt = 0; Mt < 2; ++Mt) {
                    const int rA = r0 + 16 * Mt;
                    #pragma unroll
                    for (int nt = 0; nt < 4; ++nt) {
                        const int c = wn * 32 + nt * 8 + ccol;
                        const float bi0 = B1[c], bi1 = B1[c + 1];
                        __half2 hA = __floats2half2_rn(
                            fmaxf(c1[Mt][nt][0] + bi0, 0.f),
                            fmaxf(c1[Mt][nt][1] + bi1, 0.f));
                        __half2 hB = __floats2half2_rn(
                            fmaxf(c1[Mt][nt][2] + bi0, 0.f),
                            fmaxf(c1[Mt][nt][3] + bi1, 0.f));
                        *(__half2*)(sHb + rA * HS + c)       = hA;
                        *(__half2*)(sHb + (rA + 8) * HS + c) = hB;
                    }
                }
            }
        } // q

        // ---- L3: y = relu(acc2 + b2) . w3 + b3 ----
        {
            const float* B2  = sB2 + pb * 128;
            const float* W3s = sW3 + pb * 128;
            float yv[2][2];
            #pragma unroll
            for (int Mt = 0; Mt < 2; ++Mt) {
                float pA = 0.f, pB = 0.f;
                #pragma unroll
                for (int nt = 0; nt < 8; ++nt) {
                    const int c = wn * 64 + nt * 8 + ccol;
                    const float w30 = W3s[c], w31 = W3s[c + 1];
                    const float d0 = B2[c], d1 = B2[c + 1];
                    pA = fmaf(fmaxf(acc2[Mt][nt][0] + d0, 0.f), w30, pA);
                    pA = fmaf(fmaxf(acc2[Mt][nt][1] + d1, 0.f), w31, pA);
                    pB = fmaf(fmaxf(acc2[Mt][nt][2] + d0, 0.f), w30, pB);
                    pB = fmaf(fmaxf(acc2[Mt][nt][3] + d1, 0.f), w31, pB);
                    acc2[Mt][nt][0] = 0.f; acc2[Mt][nt][1] = 0.f;
                    acc2[Mt][nt][2] = 0.f; acc2[Mt][nt][3] = 0.f;
                }
                pA += __shfl_xor_sync(0xffffffffu, pA, 1);
                pA += __shfl_xor_sync(0xffffffffu, pA, 2);
                pB += __shfl_xor_sync(0xffffffffu, pB, 1);
                pB += __shfl_xor_sync(0xffffffffu, pB, 2);
                yv[Mt][0] = pA; yv[Mt][1] = pB;
            }
            if ((lane & 3) == 0) {
                sP[wn * 128 + r0]      = yv[0][0];
                sP[wn * 128 + r0 + 8]  = yv[0][1];
                sP[wn * 128 + r0 + 16] = yv[1][0];
                sP[wn * 128 + r0 + 24] = yv[1][1];
            }
            __syncthreads();
            if (wn == 0 && (lane & 3) == 0) {
                const float b3v = sB3[pb];
                #pragma unroll
                for (int s = 0; s < 4; ++s) {
                    const int r = r0 + 8 * s;
                    const float y = sP[r] + sP[128 + r] + b3v;
                    Yc[i * BT + r] = __float2half_rn(y);
                    out[(size_t)(b0 + r) * NVAR + i] = y;
                }
            }
            __syncthreads();
        }

        // ---- gather Ac for var i+1 ----
        if (i + 1 < NVAR) {
            const int np2  = __ldg(g_pcnt + i + 1);
            const int ktc2 = __ldg(g_KT + i + 1);
            for (int idx = tid; idx < (ktc2 * 16) * BT; idx += 256) {
                int c = idx >> 7, r = idx & 127;
                __half v;
                if (c < np2)       v = Yc[__ldg(g_plist + (i + 1) * NVAR + c) * BT + r];
                else if (c == np2) v = g_Uth[(size_t)(i + 1) * BATCH + b0 + r];
                else               v = __half(0.f);
                Ac[r * AS + c] = v;
            }
        }
        // next step's barrier orders gather before L1(i+1,0)
    } // i
}

// ---------------- launch ----------------
extern "C" void kernel_launch(void* const* d_in, const int* in_sizes, int n_in,
                              void* d_out, int out_size) {
    (void)in_sizes; (void)n_in; (void)out_size;
    const float* X  = (const float*)d_in[0];
    const float* U  = (const float*)d_in[1];
    const int*   G  = (const int*)  d_in[2];
    const float* W1 = (const float*)d_in[3];
    const float* b1 = (const float*)d_in[4];
    const float* W2 = (const float*)d_in[5];
    const float* b2 = (const float*)d_in[6];
    const float* W3 = (const float*)d_in[7];
    const float* b3 = (const float*)d_in[8];
    float* out = (float*)d_out;

    sen_prep_meta<<<1, NVAR>>>(G);
    sen_prep_w1h<<<(NVAR * 4 * KTMAX * 1024 + 255) / 256, 256>>>(W1);
    sen_prep_w2h<<<(NCHUNK * W2H + 255) / 256, 256>>>(W2);
    sen_prep_ut<<<(NVAR * BATCH + 255) / 256, 256>>>(U);

    cudaFuncSetAttribute(sen_main, cudaFuncAttributeMaxDynamicSharedMemorySize, SMEM_TOTAL);
    sen_main<<<NCTA, 256, SMEM_TOTAL>>>(X, b1, b2, W3, b3, out);
}

// round 9
// speedup vs baseline: 1.1731x; 1.1731x over previous
#include <cuda_runtime.h>
#include <cuda_fp16.h>
#include <cstdint>

// ---------------- constants ----------------
#define NVAR   64
#define HID1   256
#define HID2   128
#define BATCH  16384
#define BT     128
#define NCTA   (BATCH / BT)        // 128 CTAs
#define NCHUNK 256
#define KTMAX  5
#define AS     88                  // Ac row stride (halfs)
#define HS     72                  // sH row stride (halfs)
#define YCS    136                 // Yc column stride (halfs, 272B: 16B-aligned)
#define W1SLOT 10240               // bytes per W1 smem buffer (KTMAX*1024*2)
#define W2PH   2048                // halfs per W2p chunk (32 N-cols)
#define W2CH   6144                // halfs per W2c chunk (96 N-cols)
#define HBUF   18432               // one sH buffer, bytes

// SMEM byte offsets
#define OFF_AC  0                          // 128 x 88 halfs  = 22528
#define OFF_YC  22528                      // 64 x 136 halfs  = 17408
#define OFF_H   39936                      // 2 x 18432       = 36864
#define OFF_W1  76800                      // 2 x 10240       = 20480
#define OFF_W2C 97280                      // 2 x 12288       = 24576
#define OFF_W2P 121856                     // 2 x 4096        =  8192
#define OFF_B1  130048                     // 2 x 256 f
#define OFF_B2  132096                     // 2 x 128 f
#define OFF_W3  133120                     // 2 x 128 f
#define OFF_B3  134144                     // 2 f (+pad)
#define OFF_SP  134160                     // 4 x 128 f       =  2048
#define SMEM_TOTAL 136224

// named barrier ids
#define BFULL0 1
#define BFULL1 2
#define BFREE0 3
#define BFREE1 4
#define BPROD  5
#define BCONS  6

// ---------------- device scratch ----------------
__device__ __half g_W1h[NVAR * 4 * KTMAX * 1024];  // packed compact-K, paired frag-major
__device__ __half g_W2p[NCHUNK * W2PH];            // W2 cols 0..31
__device__ __half g_W2c[NCHUNK * W2CH];            // W2 cols 32..127
__device__ __half g_Uth[NVAR * BATCH];
__device__ int    g_plist[NVAR * NVAR];
__device__ int    g_pcnt[NVAR];
__device__ int    g_KT[NVAR];
__device__ int    g_off1[NVAR];

// ---------------- helpers ----------------
static __device__ __forceinline__ void mma16(float* c, const unsigned* a,
                                             unsigned b0, unsigned b1) {
    asm volatile(
        "mma.sync.aligned.m16n8k16.row.col.f32.f16.f16.f32 "
        "{%0,%1,%2,%3},{%4,%5,%6,%7},{%8,%9},{%0,%1,%2,%3};\n"
        : "+f"(c[0]), "+f"(c[1]), "+f"(c[2]), "+f"(c[3])
        : "r"(a[0]), "r"(a[1]), "r"(a[2]), "r"(a[3]), "r"(b0), "r"(b1));
}

static __device__ __forceinline__ void ldmA(unsigned* a, uint32_t saddr) {
    asm volatile("ldmatrix.sync.aligned.m8n8.x4.shared.b16 {%0,%1,%2,%3}, [%4];"
        : "=r"(a[0]), "=r"(a[1]), "=r"(a[2]), "=r"(a[3]) : "r"(saddr));
}

static __device__ __forceinline__ void cp16(void* sdst, const void* gsrc) {
    unsigned sa = (unsigned)__cvta_generic_to_shared(sdst);
    asm volatile("cp.async.cg.shared.global [%0], [%1], 16;\n" :: "r"(sa), "l"(gsrc));
}

#define CP_COMMIT() asm volatile("cp.async.commit_group;\n" ::: "memory")
#define CP_WAIT1()  asm volatile("cp.async.wait_group 1;\n" ::: "memory")
#define BAR_SYNC(id, n)   asm volatile("bar.sync %0, %1;"   :: "r"(id), "r"(n) : "memory")
#define BAR_ARRIVE(id, n) asm volatile("bar.arrive %0, %1;" :: "r"(id), "r"(n) : "memory")

// ---------------- prep kernels ----------------
__global__ void sen_prep_meta(const int* __restrict__ G) {
    int i = threadIdx.x;
    int np = 0;
    for (int j = 0; j < i; ++j)
        if (G[j * NVAR + i] > 0) g_plist[i * NVAR + np++] = j;
    g_pcnt[i] = np;
    g_KT[i] = (np + 16) / 16;          // ceil((np+1)/16)
    __syncthreads();
    if (i == 0) {
        int off = 0;
        for (int v = 0; v < NVAR; ++v) { g_off1[v] = off; off += 4 * g_KT[v] * 1024; }
    }
}

// W1 packed compact-K, paired frag-major: chunk(i,q) = [n4=4][kt=ktc][lane=32][8 halfs]
__global__ void sen_prep_w1h(const float* __restrict__ W1) {
    int idx = blockIdx.x * blockDim.x + threadIdx.x;
    if (idx >= NVAR * 4 * KTMAX * 1024) return;
    int i    = idx / (4 * KTMAX * 1024);
    int rem  = idx % (4 * KTMAX * 1024);
    int q    = rem / (KTMAX * 1024);
    int rem2 = rem % (KTMAX * 1024);
    int n4   = rem2 / (KTMAX * 256);
    int rem3 = rem2 % (KTMAX * 256);
    int kt   = rem3 / 256;
    int f    = rem3 % 256;
    int lane = f >> 3, h = f & 7;
    int ktc = g_KT[i];
    if (kt >= ktc) return;
    int n8l = h >> 2, p = (h >> 1) & 1, e = h & 1;
    int k = kt * 16 + (lane & 3) * 2 + 8 * p + e;
    int n = q * 64 + n4 * 16 + n8l * 8 + (lane >> 2);
    int np = g_pcnt[i];
    float val = 0.f;
    if (k < np)       val = W1[(i * (NVAR + 1) + g_plist[i * NVAR + k]) * HID1 + n];
    else if (k == np) val = W1[(i * (NVAR + 1) + NVAR) * HID1 + n];
    int dst = g_off1[i] + q * ktc * 1024 + ((n4 * ktc + kt) * 32 + lane) * 8 + h;
    g_W1h[dst] = __float2half_rn(val);
}

// W2 split: n4g 0..1 -> g_W2p (cols 0..31), n4g 2..7 -> g_W2c (cols 32..127)
__global__ void sen_prep_w2(const float* __restrict__ W2) {
    int idx = blockIdx.x * blockDim.x + threadIdx.x;
    if (idx >= NCHUNK * 8192) return;
    int t    = idx / 8192;
    int rem  = idx % 8192;
    int n4g  = rem / 1024;
    int rem2 = rem % 1024;
    int kt   = rem2 / 256;
    int f    = rem2 % 256;
    int lane = f >> 3, h = f & 7;
    int n8l = h >> 2, p = (h >> 1) & 1, e = h & 1;
    int i = t >> 2, q = t & 3;
    int k = q * 64 + kt * 16 + (lane & 3) * 2 + 8 * p + e;
    int n = n4g * 16 + n8l * 8 + (lane >> 2);
    __half v = __float2half_rn(W2[(i * HID1 + k) * HID2 + n]);
    if (n4g < 2)
        g_W2p[t * W2PH + ((n4g * 4 + kt) * 32 + lane) * 8 + h] = v;
    else
        g_W2c[t * W2CH + (((n4g - 2) * 4 + kt) * 32 + lane) * 8 + h] = v;
}

__global__ void sen_prep_ut(const float* __restrict__ U) {
    int idx = blockIdx.x * blockDim.x + threadIdx.x;
    if (idx >= NVAR * BATCH) return;
    int v = idx / BATCH;
    int b = idx - v * BATCH;
    g_Uth[idx] = __float2half_rn(U[b * NVAR + v]);
}

// ---------------- main kernel: 512 threads, warp-specialized + rebalanced ----------------
__global__ void __launch_bounds__(512, 1) sen_main(
    const float* __restrict__ X,
    const float* __restrict__ b1g,
    const float* __restrict__ b2g,
    const float* __restrict__ W3g,
    const float* __restrict__ b3g,
    float* __restrict__ out)
{
    extern __shared__ char smem[];
    __half* Ac  = (__half*)(smem + OFF_AC);
    __half* Yc  = (__half*)(smem + OFF_YC);
    float*  sB1 = (float*)(smem + OFF_B1);
    float*  sB2 = (float*)(smem + OFF_B2);
    float*  sW3 = (float*)(smem + OFF_W3);
    float*  sB3 = (float*)(smem + OFF_B3);
    float*  sP  = (float*)(smem + OFF_SP);
    const uint32_t smb = (uint32_t)__cvta_generic_to_shared(smem);

    const int tid  = threadIdx.x;
    const int lane = tid & 31;
    const int w    = tid >> 5;
    const bool producer = (w < 8);
    const int wg   = w & 7;
    const int wm   = wg >> 1;               // M group 0..3 (rows 32*wm..+32)
    const int wn   = wg & 1;                // N group 0..1
    const int b0   = blockIdx.x * BT;
    const int r0   = 32 * wm + (lane >> 2);
    const int ccol = (lane & 3) * 2;
    const int tid2 = tid & 255;

    const uint32_t aAb = smb + OFF_AC +
        ((((32 * wm + (lane & 15)) * AS) + (lane >> 4) * 8) << 1);
    const uint32_t aHb = smb + OFF_H +
        ((((32 * wm + (lane & 15)) * HS) + (lane >> 4) * 8) << 1);

    // init Yc (column-major, stride YCS) from X
    for (int idx = tid; idx < NVAR * BT; idx += 512) {
        int v = idx >> 7, r = idx & 127;
        Yc[v * YCS + r] = __float2half_rn(X[(size_t)(b0 + r) * NVAR + v]);
    }
    // var-0 biases (parity 0)
    if (tid < 256) sB1[tid] = __ldg(b1g + tid);
    if (tid < 128) { sB2[tid] = __ldg(b2g + tid); sW3[tid] = __ldg(W3g + tid); }
    if (tid == 0) sB3[0] = __ldg(b3g);
    __syncthreads();

    // prologue: producers gather Ac(0) + prefetch W1(0),W2p(0); consumers W2c(0)
    if (producer) {
        const int ktc0 = __ldg(g_KT);
        const int cols = ktc0 * 16;
        for (int idx = tid2; idx < cols * 16; idx += 256) {
            int c = idx % cols, rblk = idx / cols, r = rblk * 8;
            // var0: np=0 -> col 0 = u, rest zeros
            if (c == 0) {
                uint4 v = *(const uint4*)(g_Uth + b0 + r);
                const __half* hv = (const __half*)&v;
                #pragma unroll
                for (int j = 0; j < 8; ++j) Ac[(r + j) * AS] = hv[j];
            } else {
                #pragma unroll
                for (int j = 0; j < 8; ++j) Ac[(r + j) * AS + c] = __half(0.f);
            }
        }
        char* d1 = smem + OFF_W1;
        for (int idx = tid2; idx < ktc0 * 128; idx += 256)
            cp16(d1 + idx * 16, (const char*)g_W1h + idx * 16);
        char* dp = smem + OFF_W2P;
        for (int idx = tid2; idx < 256; idx += 256)
            cp16(dp + idx * 16, (const char*)g_W2p + idx * 16);
    } else {
        char* dc = smem + OFF_W2C;
        for (int idx = tid2; idx < 768; idx += 256)
            cp16(dc + idx * 16, (const char*)g_W2c + idx * 16);
    }
    CP_COMMIT();

    float acc2[2][6][4];   // producers use [*][0..1][*]; consumers all 6
    #pragma unroll
    for (int m = 0; m < 2; ++m)
        #pragma unroll
        for (int n = 0; n < 6; ++n)
            #pragma unroll
            for (int e = 0; e < 4; ++e) acc2[m][n][e] = 0.f;

    #pragma unroll 1
    for (int i = 0; i < NVAR; ++i) {
        const int pb  = i & 1;
        const int ktc = __ldg(g_KT + i);

        if (producer) {
            // ============ producer: L1 (compact-K) + epi + L2p ============
            #pragma unroll 1
            for (int q = 0; q < 4; ++q) {
                const int t = i * 4 + q;
                const int buf = q & 1;
                BAR_SYNC(BPROD, 256);                 // W1/W2p buf (q+1)&1 free; Ac ready (q==0)
                {   // prefetch chunk t+1 (W1 + W2p)
                    int ni = (q < 3) ? i : i + 1;
                    int nq = (q + 1) & 3;
                    if (ni < NVAR) {
                        int ktn = __ldg(g_KT + ni);
                        const char* s1 = (const char*)(g_W1h + __ldg(g_off1 + ni)
                                                       + nq * ktn * 1024);
                        char* d1 = smem + OFF_W1 + ((q + 1) & 1) * W1SLOT;
                        for (int idx = tid2; idx < ktn * 128; idx += 256)
                            cp16(d1 + idx * 16, s1 + idx * 16);
                        const char* sp = (const char*)(g_W2p + (size_t)(t + 1) * W2PH);
                        char* dp = smem + OFF_W2P + ((t + 1) & 1) * 4096;
                        for (int idx = tid2; idx < 256; idx += 256)
                            cp16(dp + idx * 16, sp + idx * 16);
                    }
                }
                CP_COMMIT();
                if (q == 0 && i + 1 < NVAR)
                    sB1[((i + 1) & 1) * 256 + tid2] = __ldg(b1g + (i + 1) * HID1 + tid2);
                CP_WAIT1();
                BAR_SYNC(BPROD, 256);                 // W1(t)/W2p(t) visible

                // ---- L1(q): compact K, unrolled per ktc ----
                float c1[2][4][4];
                #pragma unroll
                for (int m = 0; m < 2; ++m)
                    #pragma unroll
                    for (int n = 0; n < 4; ++n)
                        #pragma unroll
                        for (int e = 0; e < 4; ++e) c1[m][n][e] = 0.f;
                const char* wb1 = smem + OFF_W1 + buf * W1SLOT;
#define L1K(KTC)                                                               \
                _Pragma("unroll")                                              \
                for (int kt = 0; kt < (KTC); ++kt) {                           \
                    unsigned a0[4], a1[4];                                     \
                    ldmA(a0, aAb + kt * 32);                                   \
                    ldmA(a1, aAb + kt * 32 + 16 * AS * 2);                     \
                    _Pragma("unroll")                                          \
                    for (int n4 = 0; n4 < 2; ++n4) {                           \
                        uint4 bb = *(const uint4*)(wb1 +                       \
                            ((((wn * 2 + n4) * (KTC) + kt) * 32 + lane) << 4));\
                        mma16(c1[0][2 * n4],     a0, bb.x, bb.y);              \
                        mma16(c1[0][2 * n4 + 1], a0, bb.z, bb.w);              \
                        mma16(c1[1][2 * n4],     a1, bb.x, bb.y);              \
                        mma16(c1[1][2 * n4 + 1], a1, bb.z, bb.w);              \
                    }                                                          \
                }
                switch (ktc) {
                    case 1: L1K(1); break;
                    case 2: L1K(2); break;
                    case 3: L1K(3); break;
                    case 4: L1K(4); break;
                    default: L1K(5); break;
                }
#undef L1K

                // ---- epilogue -> sH[buf] ----
                if (q >= 2) BAR_SYNC(BFREE0 + buf, 512);
                {
                    __half* sHb = (__half*)(smem + OFF_H + buf * HBUF);
                    const float* B1 = sB1 + pb * 256 + q * 64;
                    #pragma unroll
                    for (int Mt = 0; Mt < 2; ++Mt) {
                        const int rA = r0 + 16 * Mt;
                        #pragma unroll
                        for (int nt = 0; nt < 4; ++nt) {
                            const int c = wn * 32 + nt * 8 + ccol;
                            const float bi0 = B1[c], bi1 = B1[c + 1];
                            __half2 hA = __floats2half2_rn(
                                fmaxf(c1[Mt][nt][0] + bi0, 0.f),
                                fmaxf(c1[Mt][nt][1] + bi1, 0.f));
                            __half2 hB = __floats2half2_rn(
                                fmaxf(c1[Mt][nt][2] + bi0, 0.f),
                                fmaxf(c1[Mt][nt][3] + bi1, 0.f));
                            *(__half2*)(sHb + rA * HS + c)       = hA;
                            *(__half2*)(sHb + (rA + 8) * HS + c) = hB;
                        }
                    }
                }
                BAR_SYNC(BPROD, 256);                 // all producer epi writes visible
                BAR_ARRIVE(BFULL0 + buf, 512);

                // ---- L2p(q): cols 0..31, acc2[*][0..1][*] ----
                {
                    const char* wbp = smem + OFF_W2P + (t & 1) * 4096;
                    const uint32_t aH = aHb + buf * HBUF;
                    #pragma unroll
                    for (int kt = 0; kt < 4; ++kt) {
                        unsigned a0[4], a1[4];
                        ldmA(a0, aH + kt * 32);
                        ldmA(a1, aH + kt * 32 + 16 * HS * 2);
                        uint4 bb = *(const uint4*)(wbp +
                            (((wn * 4 + kt) * 32 + lane) << 4));
                        mma16(acc2[0][0], a0, bb.x, bb.y);
                        mma16(acc2[0][1], a0, bb.z, bb.w);
                        mma16(acc2[1][0], a1, bb.x, bb.y);
                        mma16(acc2[1][1], a1, bb.z, bb.w);
                    }
                }
            } // q

            // producer partials: cols wn*16..+16
            {
                const float* B2  = sB2 + pb * 128;
                const float* W3s = sW3 + pb * 128;
                #pragma unroll
                for (int Mt = 0; Mt < 2; ++Mt) {
                    float pA = 0.f, pB = 0.f;
                    #pragma unroll
                    for (int n8 = 0; n8 < 2; ++n8) {
                        const int c = wn * 16 + n8 * 8 + ccol;
                        const float w30 = W3s[c], w31 = W3s[c + 1];
                        const float d0 = B2[c], d1 = B2[c + 1];
                        pA = fmaf(fmaxf(acc2[Mt][n8][0] + d0, 0.f), w30, pA);
                        pA = fmaf(fmaxf(acc2[Mt][n8][1] + d1, 0.f), w31, pA);
                        pB = fmaf(fmaxf(acc2[Mt][n8][2] + d0, 0.f), w30, pB);
                        pB = fmaf(fmaxf(acc2[Mt][n8][3] + d1, 0.f), w31, pB);
                        acc2[Mt][n8][0] = 0.f; acc2[Mt][n8][1] = 0.f;
                        acc2[Mt][n8][2] = 0.f; acc2[Mt][n8][3] = 0.f;
                    }
                    pA += __shfl_xor_sync(0xffffffffu, pA, 1);
                    pA += __shfl_xor_sync(0xffffffffu, pA, 2);
                    pB += __shfl_xor_sync(0xffffffffu, pB, 1);
                    pB += __shfl_xor_sync(0xffffffffu, pB, 2);
                    if ((lane & 3) == 0) {
                        sP[wn * 128 + r0 + 16 * Mt]     = pA;
                        sP[wn * 128 + r0 + 16 * Mt + 8] = pB;
                    }
                }
            }
        } else {
            // ============ consumer: L2c (cols 32..127) ============
            #pragma unroll 1
            for (int q = 0; q < 4; ++q) {
                const int t = i * 4 + q;
                const int buf = q & 1;
                BAR_SYNC(BCONS, 256);
                if (t + 1 < NCHUNK) {
                    const char* sc = (const char*)(g_W2c + (size_t)(t + 1) * W2CH);
                    char* dc = smem + OFF_W2C + ((t + 1) & 1) * 12288;
                    for (int idx = tid2; idx < 768; idx += 256)
                        cp16(dc + idx * 16, sc + idx * 16);
                }
                CP_COMMIT();
                if (q == 1 && i + 1 < NVAR) {
                    const int nb = (i + 1) & 1;
                    if (tid2 < 128) {
                        sB2[nb * 128 + tid2] = __ldg(b2g + (i + 1) * HID2 + tid2);
                        sW3[nb * 128 + tid2] = __ldg(W3g + (i + 1) * HID2 + tid2);
                    }
                    if (tid2 == 0) sB3[nb] = __ldg(b3g + i + 1);
                }
                CP_WAIT1();
                BAR_SYNC(BCONS, 256);
                BAR_SYNC(BFULL0 + buf, 512);          // sH[buf] full

                const char* wbc = smem + OFF_W2C + (t & 1) * 12288;
                const uint32_t aH = aHb + buf * HBUF;
                #pragma unroll
                for (int kt = 0; kt < 4; ++kt) {
                    unsigned a0[4], a1[4];
                    ldmA(a0, aH + kt * 32);
                    ldmA(a1, aH + kt * 32 + 16 * HS * 2);
                    #pragma unroll
                    for (int n4 = 0; n4 < 3; ++n4) {
                        uint4 bb = *(const uint4*)(wbc +
                            ((((wn * 3 + n4) * 4 + kt) * 32 + lane) << 4));
                        mma16(acc2[0][2 * n4],     a0, bb.x, bb.y);
                        mma16(acc2[0][2 * n4 + 1], a0, bb.z, bb.w);
                        mma16(acc2[1][2 * n4],     a1, bb.x, bb.y);
                        mma16(acc2[1][2 * n4 + 1], a1, bb.z, bb.w);
                    }
                }
                if (q < 2) BAR_ARRIVE(BFREE0 + buf, 512);
            } // q

            // consumer partials: cols 32 + wn*48 .. +48
            {
                const float* B2  = sB2 + pb * 128;
                const float* W3s = sW3 + pb * 128;
                #pragma unroll
                for (int Mt = 0; Mt < 2; ++Mt) {
                    float pA = 0.f, pB = 0.f;
                    #pragma unroll
                    for (int n = 0; n < 6; ++n) {
                        const int c = 32 + wn * 48 + n * 8 + ccol;
                        const float w30 = W3s[c], w31 = W3s[c + 1];
                        const float d0 = B2[c], d1 = B2[c + 1];
                        pA = fmaf(fmaxf(acc2[Mt][n][0] + d0, 0.f), w30, pA);
                        pA = fmaf(fmaxf(acc2[Mt][n][1] + d1, 0.f), w31, pA);
                        pB = fmaf(fmaxf(acc2[Mt][n][2] + d0, 0.f), w30, pB);
                        pB = fmaf(fmaxf(acc2[Mt][n][3] + d1, 0.f), w31, pB);
                        acc2[Mt][n][0] = 0.f; acc2[Mt][n][1] = 0.f;
                        acc2[Mt][n][2] = 0.f; acc2[Mt][n][3] = 0.f;
                    }
                    pA += __shfl_xor_sync(0xffffffffu, pA, 1);
                    pA += __shfl_xor_sync(0xffffffffu, pA, 2);
                    pB += __shfl_xor_sync(0xffffffffu, pB, 1);
                    pB += __shfl_xor_sync(0xffffffffu, pB, 2);
                    if ((lane & 3) == 0) {
                        sP[(2 + wn) * 128 + r0 + 16 * Mt]     = pA;
                        sP[(2 + wn) * 128 + r0 + 16 * Mt + 8] = pB;
                    }
                }
            }
        }

        __syncthreads();   // all partials visible
        if (!producer && wn == 0 && (lane & 3) == 0) {
            const float b3v = sB3[pb];
            #pragma unroll
            for (int s = 0; s < 4; ++s) {
                const int r = r0 + 8 * s;
                const float y = sP[r] + sP[128 + r] + sP[256 + r] + sP[384 + r] + b3v;
                Yc[i * YCS + r] = __float2half_rn(y);
                out[(size_t)(b0 + r) * NVAR + i] = y;
            }
        }
        __syncthreads();   // Yc(i) visible

        // producers gather Ac for var i+1
        if (producer && i + 1 < NVAR) {
            const int np2  = __ldg(g_pcnt + i + 1);
            const int ktc2 = __ldg(g_KT + i + 1);
            const int cols = ktc2 * 16;
            for (int idx = tid2; idx < cols * 16; idx += 256) {
                int c = idx % cols, rblk = idx / cols, r = rblk * 8;
                if (c < np2) {
                    const int pl = __ldg(g_plist + (i + 1) * NVAR + c);
                    uint4 v = *(const uint4*)(Yc + pl * YCS + r);
                    const __half* hv = (const __half*)&v;
                    #pragma unroll
                    for (int j = 0; j < 8; ++j) Ac[(r + j) * AS + c] = hv[j];
                } else if (c == np2) {
                    uint4 v = *(const uint4*)(g_Uth + (size_t)(i + 1) * BATCH + b0 + r);
                    const __half* hv = (const __half*)&v;
                    #pragma unroll
                    for (int j = 0; j < 8; ++j) Ac[(r + j) * AS + c] = hv[j];
                } else {
                    #pragma unroll
                    for (int j = 0; j < 8; ++j) Ac[(r + j) * AS + c] = __half(0.f);
                }
            }
        }
    } // i
}

// ---------------- launch ----------------
extern "C" void kernel_launch(void* const* d_in, const int* in_sizes, int n_in,
                              void* d_out, int out_size) {
    (void)in_sizes; (void)n_in; (void)out_size;
    const float* X  = (const float*)d_in[0];
    const float* U  = (const float*)d_in[1];
    const int*   G  = (const int*)  d_in[2];
    const float* W1 = (const float*)d_in[3];
    const float* b1 = (const float*)d_in[4];
    const float* W2 = (const float*)d_in[5];
    const float* b2 = (const float*)d_in[6];
    const float* W3 = (const float*)d_in[7];
    const float* b3 = (const float*)d_in[8];
    float* out = (float*)d_out;

    sen_prep_meta<<<1, NVAR>>>(G);
    sen_prep_w1h<<<(NVAR * 4 * KTMAX * 1024 + 255) / 256, 256>>>(W1);
    sen_prep_w2<<<(NCHUNK * 8192 + 255) / 256, 256>>>(W2);
    sen_prep_ut<<<(NVAR * BATCH + 255) / 256, 256>>>(U);

    cudaFuncSetAttribute(sen_main, cudaFuncAttributeMaxDynamicSharedMemorySize, SMEM_TOTAL);
    sen_main<<<NCTA, 512, SMEM_TOTAL>>>(X, b1, b2, W3, b3, out);
}

// round 11
// speedup vs baseline: 1.3435x; 1.1453x over previous
#include <cuda_runtime.h>
#include <cuda_fp16.h>
#include <cstdint>

// ---------------- constants ----------------
#define NVAR   64
#define HID1   256
#define HID2   128
#define BATCH  16384
#define BT     128
#define NCTA   (BATCH / BT)        // 128 CTAs
#define KTMAX  5
#define AS     88                  // Ac row stride (halfs)
#define HSH    264                 // sH row stride (halfs)
#define YCS    136                 // Yc column stride (halfs)

// SMEM byte offsets
#define OFF_AC  0                          // 128 x 88 halfs   = 22528
#define OFF_YC  22528                      // 64 x 136 halfs   = 17408
#define OFF_H   39936                      // 128 x 264 halfs  = 67584
#define OFF_W1  107520                     // 1 x 40960 (max ktc=5)
#define OFF_W2  148480                     // 2 x 32768 bytes  = 65536
#define OFF_B1  214016                     // 2 x 256 f
#define OFF_B2  216064                     // 2 x 128 f
#define OFF_W3  217088                     // 2 x 128 f
#define OFF_B3  218112                     // 2 f (+pad)
#define OFF_SP  218128                     // 2 x 128 f
#define SMEM_TOTAL 219152

// ---------------- device scratch ----------------
__device__ __half g_W1h[NVAR * 2 * 8 * KTMAX * 256];  // packed compact-K frag-major
__device__ __half g_W2h[NVAR * 32768];                // per-var: h0 = halfs [0,16384), h1 = [16384,32768)
__device__ __half g_Uth[NVAR * BATCH];
__device__ int    g_plist[NVAR * NVAR];
__device__ int    g_pcnt[NVAR];
__device__ int    g_KT[NVAR];
__device__ int    g_off1[NVAR];            // halfs offset of var's W1 chunk

// ---------------- helpers ----------------
static __device__ __forceinline__ void mma16(float* c, const unsigned* a,
                                             unsigned b0, unsigned b1) {
    asm volatile(
        "mma.sync.aligned.m16n8k16.row.col.f32.f16.f16.f32 "
        "{%0,%1,%2,%3},{%4,%5,%6,%7},{%8,%9},{%0,%1,%2,%3};\n"
        : "+f"(c[0]), "+f"(c[1]), "+f"(c[2]), "+f"(c[3])
        : "r"(a[0]), "r"(a[1]), "r"(a[2]), "r"(a[3]), "r"(b0), "r"(b1));
}

static __device__ __forceinline__ void ldmA(unsigned* a, uint32_t saddr) {
    asm volatile("ldmatrix.sync.aligned.m8n8.x4.shared.b16 {%0,%1,%2,%3}, [%4];"
        : "=r"(a[0]), "=r"(a[1]), "=r"(a[2]), "=r"(a[3]) : "r"(saddr));
}

static __device__ __forceinline__ void cp16(void* sdst, const void* gsrc) {
    unsigned sa = (unsigned)__cvta_generic_to_shared(sdst);
    asm volatile("cp.async.cg.shared.global [%0], [%1], 16;\n" :: "r"(sa), "l"(gsrc));
}

#define CP_COMMIT() asm volatile("cp.async.commit_group;\n" ::: "memory")
#define CP_WAIT0()  asm volatile("cp.async.wait_group 0;\n" ::: "memory")

// ---------------- prep kernels ----------------
__global__ void sen_prep_meta(const int* __restrict__ G) {
    int i = threadIdx.x;
    int np = 0;
    for (int j = 0; j < i; ++j)
        if (G[j * NVAR + i] > 0) g_plist[i * NVAR + np++] = j;
    g_pcnt[i] = np;
    g_KT[i] = (np + 16) / 16;          // ceil((np+1)/16), <= 4
    __syncthreads();
    if (i == 0) {
        int off = 0;
        for (int v = 0; v < NVAR; ++v) { g_off1[v] = off; off += 4096 * g_KT[v]; }
    }
}

// W1 packed compact-K frag-major: chunk(i) = [hf=2][n4g=8][kt=ktc][lane=32][8 halfs]
//   k = kt*16 + (lane&3)*2 + 8p + e (compact: parents, then u, zero-pad)
//   n = hf*128 + n4g*16 + n8l*8 + (lane>>2)
__global__ void sen_prep_w1h(const float* __restrict__ W1) {
    int idx = blockIdx.x * blockDim.x + threadIdx.x;
    if (idx >= NVAR * 20480) return;
    int i    = idx / 20480;
    int rem  = idx % 20480;
    int hf   = rem / 10240;
    int rem2 = rem % 10240;
    int n4g  = rem2 / 1280;
    int rem3 = rem2 % 1280;
    int kt   = rem3 / 256;
    int f    = rem3 % 256;
    int lane = f >> 3, h = f & 7;
    int ktc = g_KT[i];
    if (kt >= ktc) return;
    int n8l = h >> 2, p = (h >> 1) & 1, e = h & 1;
    int k = kt * 16 + (lane & 3) * 2 + 8 * p + e;
    int n = hf * 128 + n4g * 16 + n8l * 8 + (lane >> 2);
    int np = g_pcnt[i];
    float val = 0.f;
    if (k < np)       val = W1[(i * (NVAR + 1) + g_plist[i * NVAR + k]) * HID1 + n];
    else if (k == np) val = W1[(i * (NVAR + 1) + NVAR) * HID1 + n];
    int dst = g_off1[i] + ((hf * 8 + n4g) * ktc + kt) * 256 + lane * 8 + h;
    g_W1h[dst] = __float2half_rn(val);
}

// W2: per var, [hf=2][n4g=8][kt=8][lane=32][8 halfs]
//   k = hf*128 + kt*16 + (lane&3)*2 + 8p + e ; n = n4g*16 + n8l*8 + (lane>>2)
__global__ void sen_prep_w2h(const float* __restrict__ W2) {
    int idx = blockIdx.x * blockDim.x + threadIdx.x;
    if (idx >= NVAR * 32768) return;
    int i    = idx / 32768;
    int rem  = idx % 32768;
    int hf   = rem / 16384;
    int rem2 = rem % 16384;
    int n4g  = rem2 / 2048;
    int rem3 = rem2 % 2048;
    int kt   = rem3 / 256;
    int f    = rem3 % 256;
    int lane = f >> 3, h = f & 7;
    int n8l = h >> 2, p = (h >> 1) & 1, e = h & 1;
    int k = hf * 128 + kt * 16 + (lane & 3) * 2 + 8 * p + e;
    int n = n4g * 16 + n8l * 8 + (lane >> 2);
    g_W2h[idx] = __float2half_rn(W2[(i * HID1 + k) * HID2 + n]);
}

__global__ void sen_prep_ut(const float* __restrict__ U) {
    int idx = blockIdx.x * blockDim.x + threadIdx.x;
    if (idx >= NVAR * BATCH) return;
    int v = idx / BATCH;
    int b = idx - v * BATCH;
    g_Uth[idx] = __float2half_rn(U[b * NVAR + v]);
}

// ---------------- main kernel: 256 threads, 2 fat phases per var ----------------
__global__ void __launch_bounds__(256, 1) sen_main(
    const float* __restrict__ X,
    const float* __restrict__ b1g,
    const float* __restrict__ b2g,
    const float* __restrict__ W3g,
    const float* __restrict__ b3g,
    float* __restrict__ out)
{
    extern __shared__ char smem[];
    __half* Ac  = (__half*)(smem + OFF_AC);
    __half* Yc  = (__half*)(smem + OFF_YC);
    __half* sH  = (__half*)(smem + OFF_H);
    float*  sB1 = (float*)(smem + OFF_B1);
    float*  sB2 = (float*)(smem + OFF_B2);
    float*  sW3 = (float*)(smem + OFF_W3);
    float*  sB3 = (float*)(smem + OFF_B3);
    float*  sP  = (float*)(smem + OFF_SP);
    const uint32_t smb = (uint32_t)__cvta_generic_to_shared(smem);

    const int tid  = threadIdx.x;
    const int lane = tid & 31;
    const int w    = tid >> 5;
    const int wm   = w >> 1;                // M group 0..3
    const int wn   = w & 1;                 // N group 0..1
    const int b0   = blockIdx.x * BT;
    const int r0   = 32 * wm + (lane >> 2);
    const int ccol = (lane & 3) * 2;

    const uint32_t aAb = smb + OFF_AC +
        ((((32 * wm + (lane & 15)) * AS) + (lane >> 4) * 8) << 1);
    const uint32_t aHb = smb + OFF_H +
        ((((32 * wm + (lane & 15)) * HSH) + (lane >> 4) * 8) << 1);

    // init Yc (column-major) from X
    for (int idx = tid; idx < NVAR * BT; idx += 256) {
        int v = idx >> 7, r = idx & 127;
        Yc[v * YCS + r] = __float2half_rn(X[(size_t)(b0 + r) * NVAR + v]);
    }
    // var-0 biases (parity 0)
    sB1[tid] = __ldg(b1g + tid);
    if (tid < 128) { sB2[tid] = __ldg(b2g + tid); sW3[tid] = __ldg(W3g + tid); }
    if (tid == 0) sB3[0] = __ldg(b3g);

    // prologue: gather Ac(0) (np=0 -> u at col 0, zeros to col 15), issue W1(0)
    {
        for (int idx = tid; idx < 16 * 16; idx += 256) {
            const int c = idx & 15, r = (idx >> 4) * 8;
            if (c == 0) {
                uint4 v = *(const uint4*)(g_Uth + b0 + r);
                const __half* hv = (const __half*)&v;
                #pragma unroll
                for (int j = 0; j < 8; ++j) Ac[(r + j) * AS] = hv[j];
            } else {
                #pragma unroll
                for (int j = 0; j < 8; ++j) Ac[(r + j) * AS + c] = __half(0.f);
            }
        }
        const int kt0 = __ldg(g_KT);
        const char* s1 = (const char*)g_W1h;
        for (int idx = tid; idx < kt0 * 512; idx += 256)
            cp16(smem + OFF_W1 + idx * 16, s1 + idx * 16);
        CP_COMMIT();
    }

    float acc2[2][8][4];
    #pragma unroll
    for (int m = 0; m < 2; ++m)
        #pragma unroll
        for (int n = 0; n < 8; ++n)
            #pragma unroll
            for (int e = 0; e < 4; ++e) acc2[m][n][e] = 0.f;

// L1 one half: accumulate c1 over compact K
#define L1H(KTC, HF)                                                         \
    _Pragma("unroll")                                                        \
    for (int m = 0; m < 2; ++m)                                              \
        _Pragma("unroll")                                                    \
        for (int n = 0; n < 8; ++n)                                          \
            _Pragma("unroll")                                                \
            for (int e = 0; e < 4; ++e) c1[m][n][e] = 0.f;                   \
    _Pragma("unroll")                                                        \
    for (int kt = 0; kt < (KTC); ++kt) {                                     \
        unsigned a0[4], a1[4];                                               \
        ldmA(a0, aAb + kt * 32);                                             \
        ldmA(a1, aAb + kt * 32 + 16 * AS * 2);                               \
        _Pragma("unroll")                                                    \
        for (int n4 = 0; n4 < 4; ++n4) {                                     \
            uint4 bb = *(const uint4*)(smem + OFF_W1 +                       \
                ((((((HF) * 8 + wn * 4 + n4) * (KTC)) + kt) * 32 + lane) << 4)); \
            mma16(c1[0][n4 * 2],     a0, bb.x, bb.y);                        \
            mma16(c1[0][n4 * 2 + 1], a0, bb.z, bb.w);                        \
            mma16(c1[1][n4 * 2],     a1, bb.x, bb.y);                        \
            mma16(c1[1][n4 * 2 + 1], a1, bb.z, bb.w);                        \
        }                                                                    \
    }

// epilogue one half: +b1, relu, fp16 -> sH cols HF*128 + wn*64 ..
#define EPI(HF) {                                                            \
    const float* B1 = sB1 + pb * 256;                                        \
    _Pragma("unroll")                                                        \
    for (int Mt = 0; Mt < 2; ++Mt) {                                         \
        const int rA = r0 + 16 * Mt;                                         \
        _Pragma("unroll")                                                    \
        for (int n = 0; n < 8; ++n) {                                        \
            const int c = (HF) * 128 + wn * 64 + n * 8 + ccol;               \
            const float bi0 = B1[c], bi1 = B1[c + 1];                        \
            __half2 hA = __floats2half2_rn(fmaxf(c1[Mt][n][0] + bi0, 0.f),   \
                                           fmaxf(c1[Mt][n][1] + bi1, 0.f));  \
            __half2 hB = __floats2half2_rn(fmaxf(c1[Mt][n][2] + bi0, 0.f),   \
                                           fmaxf(c1[Mt][n][3] + bi1, 0.f));  \
            *(__half2*)(sH + rA * HSH + c)       = hA;                       \
            *(__half2*)(sH + (rA + 8) * HSH + c) = hB;                       \
        } } }

// L2 one K-half: acc2 += sH[:, HF*128..] @ W2half
#define L2H(HF)                                                              \
    _Pragma("unroll")                                                        \
    for (int kt = 0; kt < 8; ++kt) {                                         \
        unsigned a0[4], a1[4];                                               \
        const uint32_t aH = aHb + ((HF) * 8 + kt) * 32;                      \
        ldmA(a0, aH);                                                        \
        ldmA(a1, aH + 16 * HSH * 2);                                         \
        _Pragma("unroll")                                                    \
        for (int n4 = 0; n4 < 4; ++n4) {                                     \
            uint4 bb = *(const uint4*)(smem + OFF_W2 + (HF) * 32768 +        \
                ((((wn * 4 + n4) * 8 + kt) * 32 + lane) << 4));              \
            mma16(acc2[0][n4 * 2],     a0, bb.x, bb.y);                      \
            mma16(acc2[0][n4 * 2 + 1], a0, bb.z, bb.w);                      \
            mma16(acc2[1][n4 * 2],     a1, bb.x, bb.y);                      \
            mma16(acc2[1][n4 * 2 + 1], a1, bb.z, bb.w);                      \
        }                                                                    \
    }

    #pragma unroll 1
    for (int i = 0; i < NVAR; ++i) {
        const int pb  = i & 1;
        const int ktc = __ldg(g_KT + i);

        // S1: W1(i)+biases landed; Ac(i) complete; W2 slots free
        CP_WAIT0();
        __syncthreads();

        // ---- phase A: issue W2(i) h0; L1 full width ----
        {
            const char* s2 = (const char*)(g_W2h + (size_t)i * 32768);   // h0: 32768 BYTES
            for (int idx = tid; idx < 2048; idx += 256)
                cp16(smem + OFF_W2 + idx * 16, s2 + idx * 16);
            CP_COMMIT();
        }
        {
            float c1[2][8][4];
            switch (ktc) {
                case 1: L1H(1, 0) EPI(0) L1H(1, 1) EPI(1) break;
                case 2: L1H(2, 0) EPI(0) L1H(2, 1) EPI(1) break;
                case 3: L1H(3, 0) EPI(0) L1H(3, 1) EPI(1) break;
                default: L1H(4, 0) EPI(0) L1H(4, 1) EPI(1) break;
            }
        }

        // S2: sH complete + W2h0 landed
        CP_WAIT0();
        __syncthreads();

        // ---- phase B1: issue W2 h1; L2 K-half 0; gather Ac(i+1) ----
        {
            // h1 = second 16384 HALFS of this var's block (fix: +16384 halfs, not +32768)
            const char* s2 = (const char*)(g_W2h + (size_t)i * 32768 + 16384);
            for (int idx = tid; idx < 2048; idx += 256)
                cp16(smem + OFF_W2 + 32768 + idx * 16, s2 + idx * 16);
            CP_COMMIT();
        }
        L2H(0)
        if (i + 1 < NVAR) {
            const int np2  = __ldg(g_pcnt + i + 1);
            const int ktc2 = __ldg(g_KT + i + 1);
            const int cols = ktc2 * 16;
            for (int idx = tid; idx < cols * 16; idx += 256) {
                const int c = idx % cols;
                const int r = (idx / cols) * 8;
                if (c < np2) {
                    const int pl = __ldg(g_plist + (i + 1) * NVAR + c);
                    if (pl != i) {     // pl == i only possible at c == np2-1; patched at y-write
                        uint4 v = *(const uint4*)(Yc + pl * YCS + r);
                        const __half* hv = (const __half*)&v;
                        #pragma unroll
                        for (int j = 0; j < 8; ++j) Ac[(r + j) * AS + c] = hv[j];
                    }
                } else if (c == np2) {
                    uint4 v = *(const uint4*)(g_Uth + (size_t)(i + 1) * BATCH + b0 + r);
                    const __half* hv = (const __half*)&v;
                    #pragma unroll
                    for (int j = 0; j < 8; ++j) Ac[(r + j) * AS + c] = hv[j];
                } else {
                    #pragma unroll
                    for (int j = 0; j < 8; ++j) Ac[(r + j) * AS + c] = __half(0.f);
                }
            }
        }

        // S3: W2h1 landed
        CP_WAIT0();
        __syncthreads();

        // ---- phase B2: issue W1(i+1) + biases; L2 K-half 1 ----
        if (i + 1 < NVAR) {
            const int ktn = __ldg(g_KT + i + 1);
            const char* s1 = (const char*)(g_W1h + __ldg(g_off1 + i + 1));
            for (int idx = tid; idx < ktn * 512; idx += 256)
                cp16(smem + OFF_W1 + idx * 16, s1 + idx * 16);
            const int nb = (i + 1) & 1;
            sB1[nb * 256 + tid] = __ldg(b1g + (i + 1) * HID1 + tid);
            if (tid < 128) {
                sB2[nb * 128 + tid] = __ldg(b2g + (i + 1) * HID2 + tid);
                sW3[nb * 128 + tid] = __ldg(W3g + (i + 1) * HID2 + tid);
            }
            if (tid == 0) sB3[nb] = __ldg(b3g + i + 1);
        }
        CP_COMMIT();
        L2H(1)

        // ---- L3: y = relu(acc2 + b2) . w3 + b3 ----
        int fixc = -1;
        if (i + 1 < NVAR) {
            const int np2 = __ldg(g_pcnt + i + 1);
            if (np2 > 0 && __ldg(g_plist + (i + 1) * NVAR + np2 - 1) == i)
                fixc = np2 - 1;
        }
        {
            const float* B2  = sB2 + pb * 128;
            const float* W3s = sW3 + pb * 128;
            float yv[2][2];
            #pragma unroll
            for (int Mt = 0; Mt < 2; ++Mt) {
                float pA = 0.f, pB = 0.f;
                #pragma unroll
                for (int n = 0; n < 8; ++n) {
                    const int c = wn * 64 + n * 8 + ccol;
                    const float w30 = W3s[c], w31 = W3s[c + 1];
                    const float d0 = B2[c], d1 = B2[c + 1];
                    pA = fmaf(fmaxf(acc2[Mt][n][0] + d0, 0.f), w30, pA);
                    pA = fmaf(fmaxf(acc2[Mt][n][1] + d1, 0.f), w31, pA);
                    pB = fmaf(fmaxf(acc2[Mt][n][2] + d0, 0.f), w30, pB);
                    pB = fmaf(fmaxf(acc2[Mt][n][3] + d1, 0.f), w31, pB);
                    acc2[Mt][n][0] = 0.f; acc2[Mt][n][1] = 0.f;
                    acc2[Mt][n][2] = 0.f; acc2[Mt][n][3] = 0.f;
                }
                pA += __shfl_xor_sync(0xffffffffu, pA, 1);
                pA += __shfl_xor_sync(0xffffffffu, pA, 2);
                pB += __shfl_xor_sync(0xffffffffu, pB, 1);
                pB += __shfl_xor_sync(0xffffffffu, pB, 2);
                yv[Mt][0] = pA; yv[Mt][1] = pB;
            }
            if ((lane & 3) == 0) {
                sP[wn * 128 + r0]      = yv[0][0];
                sP[wn * 128 + r0 + 8]  = yv[0][1];
                sP[wn * 128 + r0 + 16] = yv[1][0];
                sP[wn * 128 + r0 + 24] = yv[1][1];
            }
            __syncthreads();   // S4
            if (wn == 0 && (lane & 3) == 0) {
                const float b3v = sB3[pb];
                #pragma unroll
                for (int s = 0; s < 4; ++s) {
                    const int r = r0 + 8 * s;
                    const float y = sP[r] + sP[128 + r] + b3v;
                    out[(size_t)(b0 + r) * NVAR + i] = y;
                    const __half hy = __float2half_rn(y);
                    Yc[i * YCS + r] = hy;
                    if (fixc >= 0) Ac[r * AS + fixc] = hy;
                }
            }
        }
        // next iteration's S1 sync publishes y / Ac-fixup before A(i+1)
    } // i
}

#undef L1H
#undef EPI
#undef L2H

// ---------------- launch ----------------
extern "C" void kernel_launch(void* const* d_in, const int* in_sizes, int n_in,
                              void* d_out, int out_size) {
    (void)in_sizes; (void)n_in; (void)out_size;
    const float* X  = (const float*)d_in[0];
    const float* U  = (const float*)d_in[1];
    const int*   G  = (const int*)  d_in[2];
    const float* W1 = (const float*)d_in[3];
    const float* b1 = (const float*)d_in[4];
    const float* W2 = (const float*)d_in[5];
    const float* b2 = (const float*)d_in[6];
    const float* W3 = (const float*)d_in[7];
    const float* b3 = (const float*)d_in[8];
    float* out = (float*)d_out;

    sen_prep_meta<<<1, NVAR>>>(G);
    sen_prep_w1h<<<(NVAR * 20480 + 255) / 256, 256>>>(W1);
    sen_prep_w2h<<<(NVAR * 32768 + 255) / 256, 256>>>(W2);
    sen_prep_ut<<<(NVAR * BATCH + 255) / 256, 256>>>(U);

    cudaFuncSetAttribute(sen_main, cudaFuncAttributeMaxDynamicSharedMemorySize, SMEM_TOTAL);
    sen_main<<<NCTA, 256, SMEM_TOTAL>>>(X, b1, b2, W3, b3, out);
}

// round 12
// speedup vs baseline: 1.6186x; 1.2047x over previous
#include <cuda_runtime.h>
#include <cuda_fp16.h>
#include <cstdint>

// ---------------- constants ----------------
#define NVAR   64
#define HID1   256
#define HID2   128
#define BATCH  16384
#define BT     128
#define NCTA   (BATCH / BT)        // 128 CTAs
#define KTMAX  4
#define HSH    264                 // sH row stride (halfs)
#define YCS    136                 // Yc column stride (halfs); 272B, conflict-free

// SMEM byte offsets (all 16B aligned)
#define OFF_YC   0                         // 67 cols x 136 halfs = 18224 (pad to 18432)
#define OFF_H    18432                     // 128 x 264 halfs     = 67584
#define OFF_W1   86016                     // 1 x 32768 (ktc<=4)
#define OFF_W2   118784                    // 65536 (both K-halves)
#define OFF_COLS 184320                    // 2 x 80 ints = 640 (pad 768)
#define OFF_B1   185088                    // 2 x 256 f
#define OFF_B2   187136                    // 2 x 128 f
#define OFF_W3   188160                    // 2 x 128 f
#define OFF_B3   189184                    // 2 f (+pad)
#define OFF_SP   189200                    // 2 x 128 f
#define SMEM_TOTAL 190224

// ---------------- device scratch ----------------
__device__ __half g_W1h[NVAR * 16384];     // packed compact-K frag-major (4096*ktc halfs/var)
__device__ __half g_W2h[NVAR * 32768];     // per-var full W2, frag-major
__device__ __half g_Uth[NVAR * BATCH];
__device__ int    g_plist[NVAR * NVAR];
__device__ int    g_pcnt[NVAR];
__device__ int    g_KT[NVAR];
__device__ int    g_off1[NVAR];
__device__ int    g_cols[NVAR * 80];       // per-var Yc column index per compact-k

// ---------------- helpers ----------------
static __device__ __forceinline__ void mma16(float* c, const unsigned* a,
                                             unsigned b0, unsigned b1) {
    asm volatile(
        "mma.sync.aligned.m16n8k16.row.col.f32.f16.f16.f32 "
        "{%0,%1,%2,%3},{%4,%5,%6,%7},{%8,%9},{%0,%1,%2,%3};\n"
        : "+f"(c[0]), "+f"(c[1]), "+f"(c[2]), "+f"(c[3])
        : "r"(a[0]), "r"(a[1]), "r"(a[2]), "r"(a[3]), "r"(b0), "r"(b1));
}

static __device__ __forceinline__ void ldmA(unsigned* a, uint32_t saddr) {
    asm volatile("ldmatrix.sync.aligned.m8n8.x4.shared.b16 {%0,%1,%2,%3}, [%4];"
        : "=r"(a[0]), "=r"(a[1]), "=r"(a[2]), "=r"(a[3]) : "r"(saddr));
}
// transposed variant: lane -> stored column (MN-major source), delivers row-major frags
static __device__ __forceinline__ void ldmT(unsigned* a, uint32_t saddr) {
    asm volatile("ldmatrix.sync.aligned.m8n8.x4.trans.shared.b16 {%0,%1,%2,%3}, [%4];"
        : "=r"(a[0]), "=r"(a[1]), "=r"(a[2]), "=r"(a[3]) : "r"(saddr));
}

static __device__ __forceinline__ void cp16(void* sdst, const void* gsrc) {
    unsigned sa = (unsigned)__cvta_generic_to_shared(sdst);
    asm volatile("cp.async.cg.shared.global [%0], [%1], 16;\n" :: "r"(sa), "l"(gsrc));
}

#define CP_COMMIT() asm volatile("cp.async.commit_group;\n" ::: "memory")
#define CP_WAIT0()  asm volatile("cp.async.wait_group 0;\n" ::: "memory")

// ---------------- prep kernels ----------------
__global__ void sen_prep_meta(const int* __restrict__ G) {
    int i = threadIdx.x;
    int np = 0;
    for (int j = 0; j < i; ++j)
        if (G[j * NVAR + i] > 0) g_plist[i * NVAR + np++] = j;
    g_pcnt[i] = np;
    g_KT[i] = (np + 16) / 16;          // ceil((np+1)/16) <= 4
    for (int k = 0; k < 80; ++k) {
        int c;
        if (k < np)       c = g_plist[i * NVAR + k];
        else if (k == np) c = 64 + (i & 1);   // u column (parity)
        else              c = 66;             // zero column
        g_cols[i * 80 + k] = c;
    }
    __syncthreads();
    if (i == 0) {
        int off = 0;
        for (int v = 0; v < NVAR; ++v) { g_off1[v] = off; off += 4096 * g_KT[v]; }
    }
}

// W1 packed compact-K frag-major: chunk(i) = [hf=2][n4g=8][kt=ktc][lane=32][8 halfs]
__global__ void sen_prep_w1h(const float* __restrict__ W1) {
    int idx = blockIdx.x * blockDim.x + threadIdx.x;
    if (idx >= NVAR * 16384) return;
    int i    = idx / 16384;
    int rem  = idx % 16384;
    int hf   = rem / 8192;
    int rem2 = rem % 8192;
    int n4g  = rem2 / 1024;
    int rem3 = rem2 % 1024;
    int kt   = rem3 / 256;
    int f    = rem3 % 256;
    int lane = f >> 3, h = f & 7;
    int ktc = g_KT[i];
    if (kt >= ktc) return;
    int n8l = h >> 2, p = (h >> 1) & 1, e = h & 1;
    int k = kt * 16 + (lane & 3) * 2 + 8 * p + e;
    int n = hf * 128 + n4g * 16 + n8l * 8 + (lane >> 2);
    int np = g_pcnt[i];
    float val = 0.f;
    if (k < np)       val = W1[(i * (NVAR + 1) + g_plist[i * NVAR + k]) * HID1 + n];
    else if (k == np) val = W1[(i * (NVAR + 1) + NVAR) * HID1 + n];
    int dst = g_off1[i] + ((hf * 8 + n4g) * ktc + kt) * 256 + lane * 8 + h;
    g_W1h[dst] = __float2half_rn(val);
}

// W2 frag-major per var: [hf=2][n4g=8][kt=8][lane=32][8 halfs]
__global__ void sen_prep_w2h(const float* __restrict__ W2) {
    int idx = blockIdx.x * blockDim.x + threadIdx.x;
    if (idx >= NVAR * 32768) return;
    int i    = idx / 32768;
    int rem  = idx % 32768;
    int hf   = rem / 16384;
    int rem2 = rem % 16384;
    int n4g  = rem2 / 2048;
    int rem3 = rem2 % 2048;
    int kt   = rem3 / 256;
    int f    = rem3 % 256;
    int lane = f >> 3, h = f & 7;
    int n8l = h >> 2, p = (h >> 1) & 1, e = h & 1;
    int k = hf * 128 + kt * 16 + (lane & 3) * 2 + 8 * p + e;
    int n = n4g * 16 + n8l * 8 + (lane >> 2);
    g_W2h[idx] = __float2half_rn(W2[(i * HID1 + k) * HID2 + n]);
}

__global__ void sen_prep_ut(const float* __restrict__ U) {
    int idx = blockIdx.x * blockDim.x + threadIdx.x;
    if (idx >= NVAR * BATCH) return;
    int v = idx / BATCH;
    int b = idx - v * BATCH;
    g_Uth[idx] = __float2half_rn(U[b * NVAR + v]);
}

// ---------------- main kernel ----------------
__global__ void __launch_bounds__(256, 1) sen_main(
    const float* __restrict__ X,
    const float* __restrict__ b1g,
    const float* __restrict__ b2g,
    const float* __restrict__ W3g,
    const float* __restrict__ b3g,
    float* __restrict__ out)
{
    extern __shared__ char smem[];
    __half* Yc   = (__half*)(smem + OFF_YC);
    __half* sH   = (__half*)(smem + OFF_H);
    int*   sCols = (int*)  (smem + OFF_COLS);
    float*  sB1  = (float*)(smem + OFF_B1);
    float*  sB2  = (float*)(smem + OFF_B2);
    float*  sW3  = (float*)(smem + OFF_W3);
    float*  sB3  = (float*)(smem + OFF_B3);
    float*  sP   = (float*)(smem + OFF_SP);
    const uint32_t smb = (uint32_t)__cvta_generic_to_shared(smem);
    const uint32_t ycb = smb + OFF_YC;

    const int tid  = threadIdx.x;
    const int lane = tid & 31;
    const int w    = tid >> 5;
    const int wm   = w >> 1;                // M group 0..3
    const int wn   = w & 1;                 // N group 0..1
    const int b0   = blockIdx.x * BT;
    const int r0   = 32 * wm + (lane >> 2);
    const int ccol = (lane & 3) * 2;
    // indexed-ldmatrix lane params
    const int laneoff = ((lane >> 4) << 3) + (lane & 7);          // k within 16-col tile
    const uint32_t rowb2 = (uint32_t)(32 * wm + ((lane >> 3) & 1) * 8) * 2;  // row byte off

    const uint32_t aHb = smb + OFF_H +
        ((((32 * wm + (lane & 15)) * HSH) + (lane >> 4) * 8) << 1);

    // init Yc cols 0..63 from X (column-major)
    for (int idx = tid; idx < NVAR * BT; idx += 256) {
        int v = idx >> 7, r = idx & 127;
        Yc[v * YCS + r] = __float2half_rn(X[(size_t)(b0 + r) * NVAR + v]);
    }
    // zero cols 64..66 (u parity cols + zero col)
    for (int idx = tid; idx < 3 * YCS; idx += 256) {
        int c = 64 + idx / YCS, p = idx % YCS;
        Yc[c * YCS + p] = __half(0.f);
    }
    __syncthreads();
    // stage u_0 into col 64 (parity 0)
    if (tid < 16) {
        uint4 v = *(const uint4*)(g_Uth + b0 + tid * 8);
        *(uint4*)(Yc + 64 * YCS + tid * 8) = v;
    }
    // cols for var 0 (parity 0)
    if (tid < 80) sCols[tid] = __ldg(g_cols + tid);
    // var-0 biases (parity 0)
    sB1[tid] = __ldg(b1g + tid);
    if (tid < 128) { sB2[tid] = __ldg(b2g + tid); sW3[tid] = __ldg(W3g + tid); }
    if (tid == 0) sB3[0] = __ldg(b3g);
    // issue W1(0)
    {
        const int kt0 = __ldg(g_KT);
        const char* s1 = (const char*)g_W1h;
        for (int idx = tid; idx < kt0 * 512; idx += 256)
            cp16(smem + OFF_W1 + idx * 16, s1 + idx * 16);
        CP_COMMIT();
    }

    float acc2[2][8][4];
    #pragma unroll
    for (int m = 0; m < 2; ++m)
        #pragma unroll
        for (int n = 0; n < 8; ++n)
            #pragma unroll
            for (int e = 0; e < 4; ++e) acc2[m][n][e] = 0.f;

// L1 one N-half via indexed ldmatrix.trans from Yc
#define L1H(KTC, HF)                                                         \
    _Pragma("unroll")                                                        \
    for (int m = 0; m < 2; ++m)                                              \
        _Pragma("unroll")                                                    \
        for (int n = 0; n < 8; ++n)                                          \
            _Pragma("unroll")                                                \
            for (int e = 0; e < 4; ++e) c1[m][n][e] = 0.f;                   \
    _Pragma("unroll")                                                        \
    for (int kt = 0; kt < (KTC); ++kt) {                                     \
        unsigned a0[4], a1[4];                                               \
        const int sc = scp[kt * 16 + laneoff];                               \
        const uint32_t aA = ycb + (uint32_t)sc * (YCS * 2) + rowb2;          \
        ldmT(a0, aA);          /* rows 32wm..+15  */                         \
        ldmT(a1, aA + 32);     /* rows 32wm+16..+31 */                       \
        _Pragma("unroll")                                                    \
        for (int n4 = 0; n4 < 4; ++n4) {                                     \
            uint4 bb = *(const uint4*)(smem + OFF_W1 +                       \
                ((((((HF) * 8 + wn * 4 + n4) * (KTC)) + kt) * 32 + lane) << 4)); \
            mma16(c1[0][n4 * 2],     a0, bb.x, bb.y);                        \
            mma16(c1[0][n4 * 2 + 1], a0, bb.z, bb.w);                        \
            mma16(c1[1][n4 * 2],     a1, bb.x, bb.y);                        \
            mma16(c1[1][n4 * 2 + 1], a1, bb.z, bb.w);                        \
        }                                                                    \
    }

#define EPI(HF) {                                                            \
    const float* B1 = sB1 + pb * 256;                                        \
    _Pragma("unroll")                                                        \
    for (int Mt = 0; Mt < 2; ++Mt) {                                         \
        const int rA = r0 + 16 * Mt;                                         \
        _Pragma("unroll")                                                    \
        for (int n = 0; n < 8; ++n) {                                        \
            const int c = (HF) * 128 + wn * 64 + n * 8 + ccol;               \
            const float bi0 = B1[c], bi1 = B1[c + 1];                        \
            __half2 hA = __floats2half2_rn(fmaxf(c1[Mt][n][0] + bi0, 0.f),   \
                                           fmaxf(c1[Mt][n][1] + bi1, 0.f));  \
            __half2 hB = __floats2half2_rn(fmaxf(c1[Mt][n][2] + bi0, 0.f),   \
                                           fmaxf(c1[Mt][n][3] + bi1, 0.f));  \
            *(__half2*)(sH + rA * HSH + c)       = hA;                       \
            *(__half2*)(sH + (rA + 8) * HSH + c) = hB;                       \
        } } }

#define L2H(HF)                                                              \
    _Pragma("unroll")                                                        \
    for (int kt = 0; kt < 8; ++kt) {                                         \
        unsigned a0[4], a1[4];                                               \
        const uint32_t aH = aHb + ((HF) * 8 + kt) * 32;                      \
        ldmA(a0, aH);                                                        \
        ldmA(a1, aH + 16 * HSH * 2);                                         \
        _Pragma("unroll")                                                    \
        for (int n4 = 0; n4 < 4; ++n4) {                                     \
            uint4 bb = *(const uint4*)(smem + OFF_W2 + (HF) * 32768 +        \
                ((((wn * 4 + n4) * 8 + kt) * 32 + lane) << 4));              \
            mma16(acc2[0][n4 * 2],     a0, bb.x, bb.y);                      \
            mma16(acc2[0][n4 * 2 + 1], a0, bb.z, bb.w);                      \
            mma16(acc2[1][n4 * 2],     a1, bb.x, bb.y);                      \
            mma16(acc2[1][n4 * 2 + 1], a1, bb.z, bb.w);                      \
        }                                                                    \
    }

    #pragma unroll 1
    for (int i = 0; i < NVAR; ++i) {
        const int pb  = i & 1;
        const int ktc = __ldg(g_KT + i);

        // S1: W1(i) landed; Yc col i-1, u_i, sCols(i), biases(i) visible
        CP_WAIT0();
        __syncthreads();

        // ---- phase A: issue full W2(i); L1 (indexed) + epilogue -> sH ----
        {
            const char* s2 = (const char*)(g_W2h + (size_t)i * 32768);  // 64KB
            for (int idx = tid; idx < 4096; idx += 256)
                cp16(smem + OFF_W2 + idx * 16, s2 + idx * 16);
            CP_COMMIT();
        }
        {
            const int* scp = sCols + pb * 80;
            float c1[2][8][4];
            switch (ktc) {
                case 1: L1H(1, 0) EPI(0) L1H(1, 1) EPI(1) break;
                case 2: L1H(2, 0) EPI(0) L1H(2, 1) EPI(1) break;
                case 3: L1H(3, 0) EPI(0) L1H(3, 1) EPI(1) break;
                default: L1H(4, 0) EPI(0) L1H(4, 1) EPI(1) break;
            }
        }

        // S2: sH complete + full W2 landed
        CP_WAIT0();
        __syncthreads();

        // ---- phase B: issue next-var W1/cols/biases/u; L2 both halves; L3 ----
        if (i + 1 < NVAR) {
            const int ktn = __ldg(g_KT + i + 1);
            const char* s1 = (const char*)(g_W1h + __ldg(g_off1 + i + 1));
            for (int idx = tid; idx < ktn * 512; idx += 256)
                cp16(smem + OFF_W1 + idx * 16, s1 + idx * 16);
            const int nb = (i + 1) & 1;
            sB1[nb * 256 + tid] = __ldg(b1g + (i + 1) * HID1 + tid);
            if (tid < 128) {
                sB2[nb * 128 + tid] = __ldg(b2g + (i + 1) * HID2 + tid);
                sW3[nb * 128 + tid] = __ldg(W3g + (i + 1) * HID2 + tid);
            }
            if (tid == 0) sB3[nb] = __ldg(b3g + i + 1);
            if (tid < 80) sCols[nb * 80 + tid] = __ldg(g_cols + (i + 1) * 80 + tid);
            if (tid < 16) {   // stage u_{i+1} into its parity column
                uint4 v = *(const uint4*)(g_Uth + (size_t)(i + 1) * BATCH + b0 + tid * 8);
                *(uint4*)(Yc + (64 + nb) * YCS + tid * 8) = v;
            }
        }
        CP_COMMIT();

        L2H(0)
        L2H(1)

        // ---- L3: y = relu(acc2 + b2) . w3 + b3 ----
        {
            const float* B2  = sB2 + pb * 128;
            const float* W3s = sW3 + pb * 128;
            float yv[2][2];
            #pragma unroll
            for (int Mt = 0; Mt < 2; ++Mt) {
                float pA = 0.f, pB = 0.f;
                #pragma unroll
                for (int n = 0; n < 8; ++n) {
                    const int c = wn * 64 + n * 8 + ccol;
                    const float w30 = W3s[c], w31 = W3s[c + 1];
                    const float d0 = B2[c], d1 = B2[c + 1];
                    pA = fmaf(fmaxf(acc2[Mt][n][0] + d0, 0.f), w30, pA);
                    pA = fmaf(fmaxf(acc2[Mt][n][1] + d1, 0.f), w31, pA);
                    pB = fmaf(fmaxf(acc2[Mt][n][2] + d0, 0.f), w30, pB);
                    pB = fmaf(fmaxf(acc2[Mt][n][3] + d1, 0.f), w31, pB);
                    acc2[Mt][n][0] = 0.f; acc2[Mt][n][1] = 0.f;
                    acc2[Mt][n][2] = 0.f; acc2[Mt][n][3] = 0.f;
                }
                pA += __shfl_xor_sync(0xffffffffu, pA, 1);
                pA += __shfl_xor_sync(0xffffffffu, pA, 2);
                pB += __shfl_xor_sync(0xffffffffu, pB, 1);
                pB += __shfl_xor_sync(0xffffffffu, pB, 2);
                yv[Mt][0] = pA; yv[Mt][1] = pB;
            }
            if ((lane & 3) == 0) {
                sP[wn * 128 + r0]      = yv[0][0];
                sP[wn * 128 + r0 + 8]  = yv[0][1];
                sP[wn * 128 + r0 + 16] = yv[1][0];
                sP[wn * 128 + r0 + 24] = yv[1][1];
            }
            __syncthreads();   // S4
            if (wn == 0 && (lane & 3) == 0) {
                const float b3v = sB3[pb];
                #pragma unroll
                for (int s = 0; s < 4; ++s) {
                    const int r = r0 + 8 * s;
                    const float y = sP[r] + sP[128 + r] + b3v;
                    out[(size_t)(b0 + r) * NVAR + i] = y;
                    Yc[i * YCS + r] = __float2half_rn(y);   // column i, read by later vars
                }
            }
        }
        // next S1 publishes Yc col i / u / cols / biases before A(i+1)
    } // i
}

#undef L1H
#undef EPI
#undef L2H

// ---------------- launch ----------------
extern "C" void kernel_launch(void* const* d_in, const int* in_sizes, int n_in,
                              void* d_out, int out_size) {
    (void)in_sizes; (void)n_in; (void)out_size;
    const float* X  = (const float*)d_in[0];
    const float* U  = (const float*)d_in[1];
    const int*   G  = (const int*)  d_in[2];
    const float* W1 = (const float*)d_in[3];
    const float* b1 = (const float*)d_in[4];
    const float* W2 = (const float*)d_in[5];
    const float* b2 = (const float*)d_in[6];
    const float* W3 = (const float*)d_in[7];
    const float* b3 = (const float*)d_in[8];
    float* out = (float*)d_out;

    sen_prep_meta<<<1, NVAR>>>(G);
    sen_prep_w1h<<<(NVAR * 16384 + 255) / 256, 256>>>(W1);
    sen_prep_w2h<<<(NVAR * 32768 + 255) / 256, 256>>>(W2);
    sen_prep_ut<<<(NVAR * BATCH + 255) / 256, 256>>>(U);

    cudaFuncSetAttribute(sen_main, cudaFuncAttributeMaxDynamicSharedMemorySize, SMEM_TOTAL);
    sen_main<<<NCTA, 256, SMEM_TOTAL>>>(X, b1, b2, W3, b3, out);
}